// round 13
// baseline (speedup 1.0000x reference)
#include <cuda_runtime.h>
#include <cuda_fp16.h>
#include <math.h>
#include <stdint.h>

// Problem constants
#define BATCH   8
#define TLEN    4096
#define DMODEL  512
#define DIM     512
#define M_ROWS  (BATCH*TLEN)   /* 32768 */
#define N1      1024           /* interleaved: col 2n = re_n, 2n+1 = im_n */
#define CHUNK   64
#define NCHUNK  (TLEN/CHUNK)   /* 64 */

// ---------------- scratch (device globals; no allocation allowed) -----------
__device__ __half g_Buh[(size_t)M_ROWS * N1];      // 64 MB fp16 (GEMM1 out, scan in)
__device__ __half g_xhi[(size_t)M_ROWS * DMODEL];  // 32 MB
__device__ __half g_Hhi[(size_t)M_ROWS * N1];      // 64 MB
__device__ __half g_W1 [N1 * DMODEL];              // [col=2n+comp][k=512] fp16
__device__ __half g_C2 [DMODEL * N1];              // [d=512][kk=2n+comp] fp16
__device__ float2 g_lam [DIM];
__device__ float2 g_lamP[DIM];                     // Lambda^CHUNK (=^64)
__device__ float2 g_sum[NCHUNK * BATCH * DIM];     // 2 MB (L2-resident)

// ---------------- PTX helpers -----------------------------------------------
#define SWZ(o) ((o) ^ (((o) >> 3) & 0x70))

#define CP16(dst, src) \
    asm volatile("cp.async.cg.shared.global [%0], [%1], 16;" :: "r"(dst), "l"(src) : "memory")

__device__ __forceinline__ uint32_t smem_u32(const void* p) {
    uint32_t a;
    asm("{ .reg .u64 t; cvta.to.shared.u64 t, %1; cvt.u32.u64 %0, t; }" : "=r"(a) : "l"(p));
    return a;
}

#define LDSM_X4(r, addr) \
    asm volatile("ldmatrix.sync.aligned.m8n8.x4.shared.b16 {%0,%1,%2,%3}, [%4];" \
        : "=r"((r)[0]), "=r"((r)[1]), "=r"((r)[2]), "=r"((r)[3]) : "r"(addr))

#define MMA16816(c, a, b0, b1) \
    asm volatile("mma.sync.aligned.m16n8k16.row.col.f32.f16.f16.f32 " \
        "{%0,%1,%2,%3}, {%4,%5,%6,%7}, {%8,%9}, {%0,%1,%2,%3};" \
        : "+f"((c)[0]), "+f"((c)[1]), "+f"((c)[2]), "+f"((c)[3]) \
        : "r"((a)[0]), "r"((a)[1]), "r"((a)[2]), "r"((a)[3]), "r"(b0), "r"(b1))

// ---------------- prep: interleaved fp16 weights + lambda powers ------------
__global__ void prep_kernel(const float* __restrict__ B_re, const float* __restrict__ B_im,
                            const float* __restrict__ C_re, const float* __restrict__ C_im,
                            const float* __restrict__ gamma_log,
                            const float* __restrict__ nu_log,
                            const float* __restrict__ theta_log)
{
    int b = blockIdx.x;    // 0..1023 (= 2n + comp)
    int t = threadIdx.x;   // 0..511
    int nc = b >> 1, comp = b & 1;

    // W1t[col=b][k=t] = (comp ? B_im : B_re)[t][nc] * gamma_nc
    {
        float g = expf(gamma_log[nc]);
        float v = (comp ? B_im[t * DIM + nc] : B_re[t * DIM + nc]) * g;
        g_W1[b * DMODEL + t] = __float2half(v);
    }
    // C2t[d=t][kk=b] = comp ? -C_im[nc][t] : C_re[nc][t]
    {
        float v = comp ? -C_im[nc * DMODEL + t] : C_re[nc * DMODEL + t];
        g_C2[(size_t)t * N1 + b] = __float2half(v);
    }
    if (b == 0) {
        float r  = expf(-expf(nu_log[t]));
        float th = expf(theta_log[t]);
        float lr = r * cosf(th), li = r * sinf(th);
        g_lam[t] = make_float2(lr, li);
        float ar = 1.f, ai = 0.f;
        for (int k = 0; k < CHUNK; k++) {
            float nr = ar * lr - ai * li;
            float ni = ar * li + ai * lr;
            ar = nr; ai = ni;
        }
        g_lamP[t] = make_float2(ar, ai);
    }
}

// ---------------- x -> fp16 -------------------------------------------------
__global__ void convert_x(const float* __restrict__ x)
{
    size_t i = (size_t)blockIdx.x * blockDim.x + threadIdx.x;   // over 4.19M float4
    float4 v = ((const float4*)x)[i];
    __half2 a; a.x = __float2half(v.x); a.y = __float2half(v.y);
    __half2 b; b.x = __float2half(v.z); b.y = __float2half(v.w);
    __half2* H = (__half2*)g_xhi;
    H[2*i] = a; H[2*i+1] = b;
}

// ---------------- fp16 GEMM: BM=128, BN param, 4 warps, 3-stage -------------
// D[m][n] = sum_k A[m][k]*B[n][k]; fp16 K-major both, fp32 accum, SW128.
// SUMS (GEMM1 only): two 64-row chunk-local scan sums per complex column.
#define NSTAGE 3

template<int KDIM, int BN>
__device__ __forceinline__ void fill_tile(uint32_t st, int tid, int row0, int n0, int k0,
    const __half* __restrict__ A, const __half* __restrict__ Bw)
{
    constexpr int ITER = 8 + BN / 16;
#pragma unroll
    for (int i = 0; i < ITER; ++i) {
        int ch = tid + i * 128;
        if (ch < 1024) {   // A: 128 rows x 8 16B-chunks
            int r = ch >> 3, c = ch & 7;
            CP16(st + SWZ((uint32_t)(r * 128 + c * 16)),
                 A + (size_t)(row0 + r) * KDIM + k0 + c * 8);
        } else {           // B: BN rows x 8 16B-chunks
            int bc = ch - 1024;
            int r = bc >> 3, c = bc & 7;
            CP16(st + 16384 + SWZ((uint32_t)(r * 128 + c * 16)),
                 Bw + (size_t)(n0 + r) * KDIM + k0 + c * 8);
        }
    }
    asm volatile("cp.async.commit_group;" ::: "memory");
}

template<int KDIM, int BN, bool HALF_OUT, bool EPI, bool SUMS, int MAXCTA>
__global__ __launch_bounds__(128, MAXCTA) void lru_gemm(
    const __half* __restrict__ A, const __half* __restrict__ Bw,
    void* __restrict__ Cout, int Ntot,
    const float* __restrict__ xres, const float* __restrict__ Dp)
{
    constexpr int STAGE_BYTES = 16384 + BN * 128;
    constexpr int WN = BN / 2;        // warp n-extent
    constexpr int NB = WN / 8;        // 8-col fragments per warp
    constexpr int NG = WN / 16;       // 16-row B ldmatrix groups

    extern __shared__ __align__(1024) char smem[];
    const uint32_t sb = smem_u32(smem);
    const int tid = threadIdx.x;
    const int wid = tid >> 5;
    const int lane = tid & 31;
    const int warp_m = wid & 1;
    const int warp_n = wid >> 1;
    const int row0 = blockIdx.y * 128;
    const int n0   = blockIdx.x * BN;
    constexpr int NK = KDIM / 64;

    float acc[4][NB][4];
#pragma unroll
    for (int mb = 0; mb < 4; mb++)
#pragma unroll
        for (int nb = 0; nb < NB; nb++)
#pragma unroll
            for (int r = 0; r < 4; r++) acc[mb][nb][r] = 0.f;

    const int lrow  = lane & 15;
    const int khalf = lane >> 4;

    fill_tile<KDIM, BN>(sb,               tid, row0, n0, 0,  A, Bw);
    fill_tile<KDIM, BN>(sb + STAGE_BYTES, tid, row0, n0, 64, A, Bw);

    int stage = 0;
    for (int it = 0; it < NK; ++it) {
        const uint32_t st = sb + (uint32_t)stage * STAGE_BYTES;
        if (it + 2 < NK) {
            int ns = stage + 2; if (ns >= NSTAGE) ns -= NSTAGE;
            fill_tile<KDIM, BN>(sb + (uint32_t)ns * STAGE_BYTES, tid,
                                row0, n0, (it + 2) * 64, A, Bw);
            asm volatile("cp.async.wait_group 2;" ::: "memory");
        } else if (it + 1 < NK) {
            asm volatile("cp.async.wait_group 1;" ::: "memory");
        } else {
            asm volatile("cp.async.wait_group 0;" ::: "memory");
        }
        __syncthreads();

#pragma unroll
        for (int ks = 0; ks < 4; ++ks) {
            const uint32_t kb = (uint32_t)(ks * 32 + khalf * 16);
            uint32_t fa[4][4], fb[NG][4];
#pragma unroll
            for (int mb = 0; mb < 4; mb++) {
                uint32_t off = SWZ((uint32_t)((warp_m * 64 + mb * 16 + lrow) * 128) + kb);
                LDSM_X4(fa[mb], st + off);
            }
#pragma unroll
            for (int g = 0; g < NG; g++) {
                uint32_t off = SWZ((uint32_t)((warp_n * WN + g * 16 + lrow) * 128) + kb);
                LDSM_X4(fb[g], st + 16384 + off);
            }
#pragma unroll
            for (int mb = 0; mb < 4; mb++)
#pragma unroll
                for (int nb = 0; nb < NB; nb++) {
                    const int g = nb >> 1, s = nb & 1;
                    MMA16816(acc[mb][nb], fa[mb], fb[g][s], fb[g][s + 2]);
                }
        }
        __syncthreads();
        if (++stage >= NSTAGE) stage = 0;
    }

    // Epilogue: m16n8 frag -> rows lane/4 (+8), cols (lane&3)*2 (+1)
    const int erow_l = warp_m * 64 + (lane >> 2);
    const int ecol_l = warp_n * WN + (lane & 3) * 2;
#pragma unroll
    for (int mb = 0; mb < 4; mb++) {
#pragma unroll
        for (int half = 0; half < 2; half++) {
            const int row = row0 + erow_l + mb * 16 + half * 8;
            if (HALF_OUT) {
                __half* cp = (__half*)Cout + (size_t)row * Ntot;
#pragma unroll
                for (int nb = 0; nb < NB; nb++) {
                    const int col = n0 + ecol_l + nb * 8;
                    __half2 v;
                    v.x = __float2half(acc[mb][nb][half * 2]);
                    v.y = __float2half(acc[mb][nb][half * 2 + 1]);
                    *(__half2*)(cp + col) = v;
                }
            } else {
                float* cp = (float*)Cout + (size_t)row * Ntot;
                const float* xp = EPI ? (xres + (size_t)row * Ntot) : nullptr;
#pragma unroll
                for (int nb = 0; nb < NB; nb++) {
                    const int col = n0 + ecol_l + nb * 8;
                    float2 v = make_float2(acc[mb][nb][half * 2], acc[mb][nb][half * 2 + 1]);
                    if (EPI) {
                        float2 xv = *(const float2*)(xp + col);
                        float2 dv = *(const float2*)(Dp + col);
                        v.x = fmaf(dv.x, xv.x, v.x);
                        v.y = fmaf(dv.y, xv.y, v.y);
                    }
                    *(float2*)(cp + col) = v;
                }
            }
        }
    }

    if (SUMS) {
        // This CTA's 128 rows = two 64-row chunks (bb = by>>5, cc = by&31 ->
        // chunk indices 2cc, 2cc+1); columns are 64 complex n (interleaved).
        const int bb = blockIdx.y >> 5;
        const int cc = blockIdx.y & 31;
        float* tile = (float*)smem;              // 128 rows x 132 floats
        __syncthreads();                         // stages dead; reuse
#pragma unroll
        for (int mb = 0; mb < 4; mb++)
#pragma unroll
            for (int half = 0; half < 2; half++) {
                int r = erow_l + mb * 16 + half * 8;
#pragma unroll
                for (int nb = 0; nb < NB; nb++) {
                    int cl = ecol_l + nb * 8;
                    *(float2*)(tile + r * 132 + cl) =
                        make_float2(acc[mb][nb][half * 2], acc[mb][nb][half * 2 + 1]);
                }
            }
        __syncthreads();

        const int j = tid & 63;                  // complex column within tile
        const int up = tid >> 6;                 // 0: rows 0-63, 1: rows 64-127
        const int nc = (n0 >> 1) + j;
        float2 lam = g_lam[nc];
        float sr = 0.f, si = 0.f;
        const float* colp = tile + (up * 64) * 132 + 2 * j;
#pragma unroll 4
        for (int t = 0; t < 64; t++) {
            float br = colp[0], bi = colp[1];
            float nr = fmaf(lam.x, sr, fmaf(-lam.y, si, br));
            float ni = fmaf(lam.x, si, fmaf( lam.y, sr, bi));
            sr = nr; si = ni;
            colp += 132;
        }
        g_sum[(((cc << 1) | up) * 8 + bb) * 512 + nc] = make_float2(sr, si);
    }
}

// ---------------- scan: 4-state per-thread carry Horner + 64-step replay ----
// thread (b, c, n4): states n..n+3 (n = 4*n4). Carry via Horner over g_sum
// (L2-resident, 32B/step), then 64-step replay with 16B loads/stores.
__global__ void scan_carry(const float* __restrict__ h0,
                           float* __restrict__ tail, int tail_mode)
{
    int gid = blockIdx.x * blockDim.x + threadIdx.x;   // 65536
    int n = (gid & 127) * 4;
    int b = (gid >> 7) & 7;
    int c = gid >> 10;                                 // 0..63
    float2 lam0 = g_lam[n],     lam1 = g_lam[n + 1];
    float2 lam2 = g_lam[n + 2], lam3 = g_lam[n + 3];
    float2 lp0 = g_lamP[n],     lp1 = g_lamP[n + 1];
    float2 lp2 = g_lamP[n + 2], lp3 = g_lamP[n + 3];
    float4 h0v = *(const float4*)&h0[b * DIM + n];
    float c0r = h0v.x, c0i = 0.f, c1r = h0v.y, c1i = 0.f;
    float c2r = h0v.z, c2i = 0.f, c3r = h0v.w, c3i = 0.f;
    for (int j = 0; j < c; ++j) {
        const float4* sp = (const float4*)&g_sum[(j * 8 + b) * 512 + n];
        float4 sA = sp[0], sB = sp[1];
        float n0r = fmaf(lp0.x, c0r, fmaf(-lp0.y, c0i, sA.x));
        float n0i = fmaf(lp0.x, c0i, fmaf( lp0.y, c0r, sA.y));
        float n1r = fmaf(lp1.x, c1r, fmaf(-lp1.y, c1i, sA.z));
        float n1i = fmaf(lp1.x, c1i, fmaf( lp1.y, c1r, sA.w));
        float n2r = fmaf(lp2.x, c2r, fmaf(-lp2.y, c2i, sB.x));
        float n2i = fmaf(lp2.x, c2i, fmaf( lp2.y, c2r, sB.y));
        float n3r = fmaf(lp3.x, c3r, fmaf(-lp3.y, c3i, sB.z));
        float n3i = fmaf(lp3.x, c3i, fmaf( lp3.y, c3r, sB.w));
        c0r = n0r; c0i = n0i; c1r = n1r; c1i = n1i;
        c2r = n2r; c2i = n2i; c3r = n3r; c3i = n3i;
    }
    size_t base = (size_t)(b * TLEN + c * CHUNK) * N1 + 2 * n;
    const uint4* p = (const uint4*)(g_Buh + base);     // 16B = 4 complex
    uint4* ph = (uint4*)(g_Hhi + base);
#pragma unroll 8
    for (int t = 0; t < CHUNK; t++) {
        uint4 raw = __ldcs(p);                          // streaming: no reuse
        float2 b0 = __half22float2(*reinterpret_cast<const __half2*>(&raw.x));
        float2 b1 = __half22float2(*reinterpret_cast<const __half2*>(&raw.y));
        float2 b2 = __half22float2(*reinterpret_cast<const __half2*>(&raw.z));
        float2 b3 = __half22float2(*reinterpret_cast<const __half2*>(&raw.w));
        float n0r = fmaf(lam0.x, c0r, fmaf(-lam0.y, c0i, b0.x));
        float n0i = fmaf(lam0.x, c0i, fmaf( lam0.y, c0r, b0.y));
        float n1r = fmaf(lam1.x, c1r, fmaf(-lam1.y, c1i, b1.x));
        float n1i = fmaf(lam1.x, c1i, fmaf( lam1.y, c1r, b1.y));
        float n2r = fmaf(lam2.x, c2r, fmaf(-lam2.y, c2i, b2.x));
        float n2i = fmaf(lam2.x, c2i, fmaf( lam2.y, c2r, b2.y));
        float n3r = fmaf(lam3.x, c3r, fmaf(-lam3.y, c3i, b3.x));
        float n3i = fmaf(lam3.x, c3i, fmaf( lam3.y, c3r, b3.y));
        c0r = n0r; c0i = n0i; c1r = n1r; c1i = n1i;
        c2r = n2r; c2i = n2i; c3r = n3r; c3i = n3i;
        __half2 v0; v0.x = __float2half(n0r); v0.y = __float2half(n0i);
        __half2 v1; v1.x = __float2half(n1r); v1.y = __float2half(n1i);
        __half2 v2; v2.x = __float2half(n2r); v2.y = __float2half(n2i);
        __half2 v3; v3.x = __float2half(n3r); v3.y = __float2half(n3i);
        uint4 outv;
        outv.x = *reinterpret_cast<uint32_t*>(&v0);
        outv.y = *reinterpret_cast<uint32_t*>(&v1);
        outv.z = *reinterpret_cast<uint32_t*>(&v2);
        outv.w = *reinterpret_cast<uint32_t*>(&v3);
        ph[0] = outv;
        p += N1 / 8; ph += N1 / 8;
    }
    if (c == NCHUNK - 1) {
        if (tail_mode == 2) {
            *(float4*)&tail[(b * DIM + n) * 2]     = make_float4(c0r, c0i, c1r, c1i);
            *(float4*)&tail[(b * DIM + n) * 2 + 4] = make_float4(c2r, c2i, c3r, c3i);
        } else if (tail_mode == 1) {
            *(float4*)&tail[b * DIM + n] = make_float4(c0r, c1r, c2r, c3r);
        }
    }
}

// ---------------- launch ----------------------------------------------------
extern "C" void kernel_launch(void* const* d_in, const int* in_sizes, int n_in,
                              void* d_out, int out_size)
{
    const float* x         = (const float*)d_in[0];
    const float* h0        = (const float*)d_in[1];
    const float* nu_log    = (const float*)d_in[2];
    const float* theta_log = (const float*)d_in[3];
    const float* B_re      = (const float*)d_in[4];
    const float* B_im      = (const float*)d_in[5];
    const float* C_re      = (const float*)d_in[6];
    const float* C_im      = (const float*)d_in[7];
    const float* D_param   = (const float*)d_in[8];
    const float* gamma_log = (const float*)d_in[9];
    float* out = (float*)d_out;

    __half *pBuh, *pxhi, *pHhi, *pW1, *pC2;
    cudaGetSymbolAddress((void**)&pBuh, g_Buh);
    cudaGetSymbolAddress((void**)&pxhi, g_xhi);
    cudaGetSymbolAddress((void**)&pHhi, g_Hhi);
    cudaGetSymbolAddress((void**)&pW1,  g_W1);
    cudaGetSymbolAddress((void**)&pC2,  g_C2);

    const int SMEM1 = NSTAGE * (16384 + 128 * 128);   // 98304
    const int SMEM2 = NSTAGE * (16384 + 64 * 128);    // 73728
    cudaFuncSetAttribute((const void*)lru_gemm<512, 128, true, false, true, 2>,
                         cudaFuncAttributeMaxDynamicSharedMemorySize, SMEM1);
    cudaFuncSetAttribute((const void*)lru_gemm<1024, 64, false, true, false, 3>,
                         cudaFuncAttributeMaxDynamicSharedMemorySize, SMEM2);

    // 1) weights + lambda, x convert
    prep_kernel<<<1024, 512>>>(B_re, B_im, C_re, C_im, gamma_log, nu_log, theta_log);
    convert_x<<<(M_ROWS * DMODEL / 4) / 256, 256>>>(x);

    // 2) GEMM1 + fused chunk sums: Bu[32768 x 1024] = x @ W1 (interleaved)
    lru_gemm<512, 128, true, false, true, 2><<<dim3(N1 / 128, M_ROWS / 128), 128, SMEM1>>>(
        pxhi, pW1, pBuh, N1, nullptr, nullptr);

    // 3) scan with per-thread carry reconstruction (Bu fp16 -> H fp16)
    const long long y_elems = (long long)M_ROWS * DMODEL;
    long long tail_elems = (long long)out_size - y_elems;
    int tail_mode = 0;
    if (tail_elems >= 2LL * BATCH * DIM)           tail_mode = 2;
    else if (tail_elems >= (long long)BATCH * DIM) tail_mode = 1;
    scan_carry<<<(NCHUNK * BATCH * DIM / 4) / 256, 256>>>(h0, out + y_elems, tail_mode);

    // 4) GEMM2: y[32768 x 512] = H @ C2 + D*x (fp32 out, 128x64 tiles)
    lru_gemm<1024, 64, false, true, false, 3><<<dim3(DMODEL / 64, M_ROWS / 128), 128, SMEM2>>>(
        pHhi, pC2, out, DMODEL, x, D_param);
}

// round 14
// speedup vs baseline: 1.1402x; 1.1402x over previous
#include <cuda_runtime.h>
#include <cuda_fp16.h>
#include <math.h>
#include <stdint.h>

// Problem constants
#define BATCH   8
#define TLEN    4096
#define DMODEL  512
#define DIM     512
#define M_ROWS  (BATCH*TLEN)   /* 32768 */
#define N1      1024           /* interleaved: col 2n = re_n, 2n+1 = im_n */
#define CHUNK   64
#define NCHUNK  (TLEN/CHUNK)   /* 64 */

// ---------------- scratch (device globals; no allocation allowed) -----------
__device__ __half g_Buh[(size_t)M_ROWS * N1];      // 64 MB fp16 (GEMM1 out, scan in)
__device__ __half g_xhi[(size_t)M_ROWS * DMODEL];  // 32 MB
__device__ __half g_Hhi[(size_t)M_ROWS * N1];      // 64 MB
__device__ __half g_W1 [N1 * DMODEL];              // [col=2n+comp][k=512] fp16
__device__ __half g_C2 [DMODEL * N1];              // [d=512][kk=2n+comp] fp16
__device__ float2 g_lam [DIM];
__device__ float2 g_lamP[DIM];                     // Lambda^CHUNK (=^64)
__device__ float2 g_sum[NCHUNK * BATCH * DIM];     // 2 MB (L2-resident)

// ---------------- PTX helpers -----------------------------------------------
#define SWZ(o) ((o) ^ (((o) >> 3) & 0x70))

#define CP16(dst, src) \
    asm volatile("cp.async.cg.shared.global [%0], [%1], 16;" :: "r"(dst), "l"(src) : "memory")

__device__ __forceinline__ uint32_t smem_u32(const void* p) {
    uint32_t a;
    asm("{ .reg .u64 t; cvta.to.shared.u64 t, %1; cvt.u32.u64 %0, t; }" : "=r"(a) : "l"(p));
    return a;
}

#define LDSM_X4(r, addr) \
    asm volatile("ldmatrix.sync.aligned.m8n8.x4.shared.b16 {%0,%1,%2,%3}, [%4];" \
        : "=r"((r)[0]), "=r"((r)[1]), "=r"((r)[2]), "=r"((r)[3]) : "r"(addr))

#define MMA16816(c, a, b0, b1) \
    asm volatile("mma.sync.aligned.m16n8k16.row.col.f32.f16.f16.f32 " \
        "{%0,%1,%2,%3}, {%4,%5,%6,%7}, {%8,%9}, {%0,%1,%2,%3};" \
        : "+f"((c)[0]), "+f"((c)[1]), "+f"((c)[2]), "+f"((c)[3]) \
        : "r"((a)[0]), "r"((a)[1]), "r"((a)[2]), "r"((a)[3]), "r"(b0), "r"(b1))

// ---------------- prep: interleaved fp16 weights + lambda powers ------------
__global__ void prep_kernel(const float* __restrict__ B_re, const float* __restrict__ B_im,
                            const float* __restrict__ C_re, const float* __restrict__ C_im,
                            const float* __restrict__ gamma_log,
                            const float* __restrict__ nu_log,
                            const float* __restrict__ theta_log)
{
    int b = blockIdx.x;    // 0..1023 (= 2n + comp)
    int t = threadIdx.x;   // 0..511
    int nc = b >> 1, comp = b & 1;

    // W1t[col=b][k=t] = (comp ? B_im : B_re)[t][nc] * gamma_nc
    {
        float g = expf(gamma_log[nc]);
        float v = (comp ? B_im[t * DIM + nc] : B_re[t * DIM + nc]) * g;
        g_W1[b * DMODEL + t] = __float2half(v);
    }
    // C2t[d=t][kk=b] = comp ? -C_im[nc][t] : C_re[nc][t]
    {
        float v = comp ? -C_im[nc * DMODEL + t] : C_re[nc * DMODEL + t];
        g_C2[(size_t)t * N1 + b] = __float2half(v);
    }
    if (b == 0) {
        float r  = expf(-expf(nu_log[t]));
        float th = expf(theta_log[t]);
        float lr = r * cosf(th), li = r * sinf(th);
        g_lam[t] = make_float2(lr, li);
        float ar = 1.f, ai = 0.f;
        for (int k = 0; k < CHUNK; k++) {
            float nr = ar * lr - ai * li;
            float ni = ar * li + ai * lr;
            ar = nr; ai = ni;
        }
        g_lamP[t] = make_float2(ar, ai);
    }
}

// ---------------- x -> fp16 -------------------------------------------------
__global__ void convert_x(const float* __restrict__ x)
{
    size_t i = (size_t)blockIdx.x * blockDim.x + threadIdx.x;   // over 4.19M float4
    float4 v = ((const float4*)x)[i];
    __half2 a; a.x = __float2half(v.x); a.y = __float2half(v.y);
    __half2 b; b.x = __float2half(v.z); b.y = __float2half(v.w);
    __half2* H = (__half2*)g_xhi;
    H[2*i] = a; H[2*i+1] = b;
}

// ---------------- fp16 GEMM: BM=128, BN param, 4 warps, 3-stage -------------
// D[m][n] = sum_k A[m][k]*B[n][k]; fp16 K-major both, fp32 accum, SW128.
// SUMS (GEMM1 only): two 64-row chunk-local scan sums per complex column.
#define NSTAGE 3

template<int KDIM, int BN>
__device__ __forceinline__ void fill_tile(uint32_t st, int tid, int row0, int n0, int k0,
    const __half* __restrict__ A, const __half* __restrict__ Bw)
{
    constexpr int ITER = 8 + BN / 16;
#pragma unroll
    for (int i = 0; i < ITER; ++i) {
        int ch = tid + i * 128;
        if (ch < 1024) {   // A: 128 rows x 8 16B-chunks
            int r = ch >> 3, c = ch & 7;
            CP16(st + SWZ((uint32_t)(r * 128 + c * 16)),
                 A + (size_t)(row0 + r) * KDIM + k0 + c * 8);
        } else {           // B: BN rows x 8 16B-chunks
            int bc = ch - 1024;
            int r = bc >> 3, c = bc & 7;
            CP16(st + 16384 + SWZ((uint32_t)(r * 128 + c * 16)),
                 Bw + (size_t)(n0 + r) * KDIM + k0 + c * 8);
        }
    }
    asm volatile("cp.async.commit_group;" ::: "memory");
}

template<int KDIM, int BN, bool HALF_OUT, bool EPI, bool SUMS, int MAXCTA>
__global__ __launch_bounds__(128, MAXCTA) void lru_gemm(
    const __half* __restrict__ A, const __half* __restrict__ Bw,
    void* __restrict__ Cout, int Ntot,
    const float* __restrict__ xres, const float* __restrict__ Dp)
{
    constexpr int STAGE_BYTES = 16384 + BN * 128;
    constexpr int WN = BN / 2;        // warp n-extent
    constexpr int NB = WN / 8;        // 8-col fragments per warp
    constexpr int NG = WN / 16;       // 16-row B ldmatrix groups

    extern __shared__ __align__(1024) char smem[];
    const uint32_t sb = smem_u32(smem);
    const int tid = threadIdx.x;
    const int wid = tid >> 5;
    const int lane = tid & 31;
    const int warp_m = wid & 1;
    const int warp_n = wid >> 1;
    const int row0 = blockIdx.y * 128;
    const int n0   = blockIdx.x * BN;
    constexpr int NK = KDIM / 64;

    float acc[4][NB][4];
#pragma unroll
    for (int mb = 0; mb < 4; mb++)
#pragma unroll
        for (int nb = 0; nb < NB; nb++)
#pragma unroll
            for (int r = 0; r < 4; r++) acc[mb][nb][r] = 0.f;

    const int lrow  = lane & 15;
    const int khalf = lane >> 4;

    fill_tile<KDIM, BN>(sb,               tid, row0, n0, 0,  A, Bw);
    fill_tile<KDIM, BN>(sb + STAGE_BYTES, tid, row0, n0, 64, A, Bw);

    int stage = 0;
    for (int it = 0; it < NK; ++it) {
        const uint32_t st = sb + (uint32_t)stage * STAGE_BYTES;
        if (it + 2 < NK) {
            int ns = stage + 2; if (ns >= NSTAGE) ns -= NSTAGE;
            fill_tile<KDIM, BN>(sb + (uint32_t)ns * STAGE_BYTES, tid,
                                row0, n0, (it + 2) * 64, A, Bw);
            asm volatile("cp.async.wait_group 2;" ::: "memory");
        } else if (it + 1 < NK) {
            asm volatile("cp.async.wait_group 1;" ::: "memory");
        } else {
            asm volatile("cp.async.wait_group 0;" ::: "memory");
        }
        __syncthreads();

#pragma unroll
        for (int ks = 0; ks < 4; ++ks) {
            const uint32_t kb = (uint32_t)(ks * 32 + khalf * 16);
            uint32_t fa[4][4], fb[NG][4];
#pragma unroll
            for (int mb = 0; mb < 4; mb++) {
                uint32_t off = SWZ((uint32_t)((warp_m * 64 + mb * 16 + lrow) * 128) + kb);
                LDSM_X4(fa[mb], st + off);
            }
#pragma unroll
            for (int g = 0; g < NG; g++) {
                uint32_t off = SWZ((uint32_t)((warp_n * WN + g * 16 + lrow) * 128) + kb);
                LDSM_X4(fb[g], st + 16384 + off);
            }
#pragma unroll
            for (int mb = 0; mb < 4; mb++)
#pragma unroll
                for (int nb = 0; nb < NB; nb++) {
                    const int g = nb >> 1, s = nb & 1;
                    MMA16816(acc[mb][nb], fa[mb], fb[g][s], fb[g][s + 2]);
                }
        }
        __syncthreads();
        if (++stage >= NSTAGE) stage = 0;
    }

    // Epilogue: m16n8 frag -> rows lane/4 (+8), cols (lane&3)*2 (+1)
    const int erow_l = warp_m * 64 + (lane >> 2);
    const int ecol_l = warp_n * WN + (lane & 3) * 2;
#pragma unroll
    for (int mb = 0; mb < 4; mb++) {
#pragma unroll
        for (int half = 0; half < 2; half++) {
            const int row = row0 + erow_l + mb * 16 + half * 8;
            if (HALF_OUT) {
                __half* cp = (__half*)Cout + (size_t)row * Ntot;
#pragma unroll
                for (int nb = 0; nb < NB; nb++) {
                    const int col = n0 + ecol_l + nb * 8;
                    __half2 v;
                    v.x = __float2half(acc[mb][nb][half * 2]);
                    v.y = __float2half(acc[mb][nb][half * 2 + 1]);
                    *(__half2*)(cp + col) = v;
                }
            } else {
                float* cp = (float*)Cout + (size_t)row * Ntot;
                const float* xp = EPI ? (xres + (size_t)row * Ntot) : nullptr;
#pragma unroll
                for (int nb = 0; nb < NB; nb++) {
                    const int col = n0 + ecol_l + nb * 8;
                    float2 v = make_float2(acc[mb][nb][half * 2], acc[mb][nb][half * 2 + 1]);
                    if (EPI) {
                        float2 xv = *(const float2*)(xp + col);
                        float2 dv = *(const float2*)(Dp + col);
                        v.x = fmaf(dv.x, xv.x, v.x);
                        v.y = fmaf(dv.y, xv.y, v.y);
                    }
                    *(float2*)(cp + col) = v;
                }
            }
        }
    }

    if (SUMS) {
        // This CTA's 128 rows = two 64-row chunks (bb = by>>5, cc = by&31 ->
        // chunk indices 2cc, 2cc+1); columns are 64 complex n (interleaved).
        const int bb = blockIdx.y >> 5;
        const int cc = blockIdx.y & 31;
        float* tile = (float*)smem;              // 128 rows x 132 floats
        __syncthreads();                         // stages dead; reuse
#pragma unroll
        for (int mb = 0; mb < 4; mb++)
#pragma unroll
            for (int half = 0; half < 2; half++) {
                int r = erow_l + mb * 16 + half * 8;
#pragma unroll
                for (int nb = 0; nb < NB; nb++) {
                    int cl = ecol_l + nb * 8;
                    *(float2*)(tile + r * 132 + cl) =
                        make_float2(acc[mb][nb][half * 2], acc[mb][nb][half * 2 + 1]);
                }
            }
        __syncthreads();

        const int j = tid & 63;                  // complex column within tile
        const int up = tid >> 6;                 // 0: rows 0-63, 1: rows 64-127
        const int nc = (n0 >> 1) + j;
        float2 lam = g_lam[nc];
        float sr = 0.f, si = 0.f;
        const float* colp = tile + (up * 64) * 132 + 2 * j;
#pragma unroll 4
        for (int t = 0; t < 64; t++) {
            float br = colp[0], bi = colp[1];
            float nr = fmaf(lam.x, sr, fmaf(-lam.y, si, br));
            float ni = fmaf(lam.x, si, fmaf( lam.y, sr, bi));
            sr = nr; si = ni;
            colp += 132;
        }
        g_sum[(((cc << 1) | up) * 8 + bb) * 512 + nc] = make_float2(sr, si);
    }
}

// ---------------- scan: 2-state carry Horner + 8-deep pipelined replay ------
// thread (b, c, n2): states n = 2*n2, 2*n2+1. Carry via Horner over g_sum
// (L2-resident), then 64-step replay with a manual 8-deep load pipeline so
// LDGs are issued 8 iterations ahead of use (defeats alias serialization).
__global__ void scan_carry(const float* __restrict__ h0,
                           float* __restrict__ tail, int tail_mode)
{
    int gid = blockIdx.x * blockDim.x + threadIdx.x;   // 131072
    int n2 = gid & 255;
    int n  = n2 * 2;
    int b  = (gid >> 8) & 7;
    int c  = gid >> 11;                                // 0..63
    float2 lam0 = g_lam[n], lam1 = g_lam[n + 1];
    float2 lp0  = g_lamP[n], lp1 = g_lamP[n + 1];
    float c0r = h0[b * DIM + n],     c0i = 0.f;
    float c1r = h0[b * DIM + n + 1], c1i = 0.f;
    for (int j = 0; j < c; ++j) {
        float4 s = *(const float4*)&g_sum[(j * 8 + b) * 512 + n];
        float n0r = fmaf(lp0.x, c0r, fmaf(-lp0.y, c0i, s.x));
        float n0i = fmaf(lp0.x, c0i, fmaf( lp0.y, c0r, s.y));
        float n1r = fmaf(lp1.x, c1r, fmaf(-lp1.y, c1i, s.z));
        float n1i = fmaf(lp1.x, c1i, fmaf( lp1.y, c1r, s.w));
        c0r = n0r; c0i = n0i; c1r = n1r; c1i = n1i;
    }
    size_t base = (size_t)(b * TLEN + c * CHUNK) * N1 + 2 * n;
    const uint2* p = (const uint2*)(g_Buh + base);     // 8B = 2 complex (n, n+1)
    uint2* ph = (uint2*)(g_Hhi + base);

    uint2 buf[8];
#pragma unroll
    for (int i = 0; i < 8; i++) buf[i] = __ldcs(p + (size_t)i * (N1 / 4));

    for (int blk = 0; blk < 8; ++blk) {
        const uint2* pn = p + (size_t)(blk + 1) * 8 * (N1 / 4);
#pragma unroll
        for (int u = 0; u < 8; ++u) {
            uint2 raw = buf[u];
            if (blk < 7) buf[u] = __ldcs(pn + (size_t)u * (N1 / 4));  // load +8 ahead
            float2 b0 = __half22float2(*reinterpret_cast<const __half2*>(&raw.x));
            float2 b1 = __half22float2(*reinterpret_cast<const __half2*>(&raw.y));
            float n0r = fmaf(lam0.x, c0r, fmaf(-lam0.y, c0i, b0.x));
            float n0i = fmaf(lam0.x, c0i, fmaf( lam0.y, c0r, b0.y));
            float n1r = fmaf(lam1.x, c1r, fmaf(-lam1.y, c1i, b1.x));
            float n1i = fmaf(lam1.x, c1i, fmaf( lam1.y, c1r, b1.y));
            c0r = n0r; c0i = n0i; c1r = n1r; c1i = n1i;
            __half2 v0; v0.x = __float2half(n0r); v0.y = __float2half(n0i);
            __half2 v1; v1.x = __float2half(n1r); v1.y = __float2half(n1i);
            uint2 outv;
            outv.x = *reinterpret_cast<uint32_t*>(&v0);
            outv.y = *reinterpret_cast<uint32_t*>(&v1);
            ph[(size_t)(blk * 8 + u) * (N1 / 4)] = outv;
        }
    }
    if (c == NCHUNK - 1) {
        if (tail_mode == 2) {
            *(float4*)&tail[(b * DIM + n) * 2] = make_float4(c0r, c0i, c1r, c1i);
        } else if (tail_mode == 1) {
            *(float2*)&tail[b * DIM + n] = make_float2(c0r, c1r);
        }
    }
}

// ---------------- launch ----------------------------------------------------
extern "C" void kernel_launch(void* const* d_in, const int* in_sizes, int n_in,
                              void* d_out, int out_size)
{
    const float* x         = (const float*)d_in[0];
    const float* h0        = (const float*)d_in[1];
    const float* nu_log    = (const float*)d_in[2];
    const float* theta_log = (const float*)d_in[3];
    const float* B_re      = (const float*)d_in[4];
    const float* B_im      = (const float*)d_in[5];
    const float* C_re      = (const float*)d_in[6];
    const float* C_im      = (const float*)d_in[7];
    const float* D_param   = (const float*)d_in[8];
    const float* gamma_log = (const float*)d_in[9];
    float* out = (float*)d_out;

    __half *pBuh, *pxhi, *pHhi, *pW1, *pC2;
    cudaGetSymbolAddress((void**)&pBuh, g_Buh);
    cudaGetSymbolAddress((void**)&pxhi, g_xhi);
    cudaGetSymbolAddress((void**)&pHhi, g_Hhi);
    cudaGetSymbolAddress((void**)&pW1,  g_W1);
    cudaGetSymbolAddress((void**)&pC2,  g_C2);

    const int SMEM1 = NSTAGE * (16384 + 128 * 128);   // 98304
    const int SMEM2 = NSTAGE * (16384 + 64 * 128);    // 73728
    cudaFuncSetAttribute((const void*)lru_gemm<512, 128, true, false, true, 2>,
                         cudaFuncAttributeMaxDynamicSharedMemorySize, SMEM1);
    cudaFuncSetAttribute((const void*)lru_gemm<1024, 64, false, true, false, 3>,
                         cudaFuncAttributeMaxDynamicSharedMemorySize, SMEM2);

    // 1) weights + lambda, x convert
    prep_kernel<<<1024, 512>>>(B_re, B_im, C_re, C_im, gamma_log, nu_log, theta_log);
    convert_x<<<(M_ROWS * DMODEL / 4) / 256, 256>>>(x);

    // 2) GEMM1 + fused chunk sums: Bu[32768 x 1024] = x @ W1 (interleaved)
    lru_gemm<512, 128, true, false, true, 2><<<dim3(N1 / 128, M_ROWS / 128), 128, SMEM1>>>(
        pxhi, pW1, pBuh, N1, nullptr, nullptr);

    // 3) scan with per-thread carry reconstruction (Bu fp16 -> H fp16)
    const long long y_elems = (long long)M_ROWS * DMODEL;
    long long tail_elems = (long long)out_size - y_elems;
    int tail_mode = 0;
    if (tail_elems >= 2LL * BATCH * DIM)           tail_mode = 2;
    else if (tail_elems >= (long long)BATCH * DIM) tail_mode = 1;
    scan_carry<<<(NCHUNK * BATCH * DIM / 2) / 256, 256>>>(h0, out + y_elems, tail_mode);

    // 4) GEMM2: y[32768 x 512] = H @ C2 + D*x (fp32 out, 128x64 tiles)
    lru_gemm<1024, 64, false, true, false, 3><<<dim3(DMODEL / 64, M_ROWS / 128), 128, SMEM2>>>(
        pHhi, pC2, out, DMODEL, x, D_param);
}

// round 15
// speedup vs baseline: 1.1739x; 1.0295x over previous
#include <cuda_runtime.h>
#include <cuda_fp16.h>
#include <math.h>
#include <stdint.h>

// Problem constants
#define BATCH   8
#define TLEN    4096
#define DMODEL  512
#define DIM     512
#define M_ROWS  (BATCH*TLEN)   /* 32768 */
#define N1      1024           /* interleaved: col 2n = re_n, 2n+1 = im_n */
#define CHUNK   64
#define NCHUNK  (TLEN/CHUNK)   /* 64 */

// ---------------- scratch (device globals; no allocation allowed) -----------
__device__ __half g_Buh[(size_t)M_ROWS * N1];      // 64 MB fp16 (GEMM1 out, scan in)
__device__ __half g_xhi[(size_t)M_ROWS * DMODEL];  // 32 MB
__device__ __half g_Hhi[(size_t)M_ROWS * N1];      // 64 MB
__device__ __half g_W1 [N1 * DMODEL];              // [col=2n+comp][k=512] fp16
__device__ __half g_C2 [DMODEL * N1];              // [d=512][kk=2n+comp] fp16
__device__ float2 g_lam [DIM];
__device__ float2 g_lamP[DIM];                     // Lambda^CHUNK (=^64)
__device__ float2 g_sum[NCHUNK * BATCH * DIM];     // 2 MB (L2-resident)

// ---------------- PTX helpers -----------------------------------------------
#define SWZ(o) ((o) ^ (((o) >> 3) & 0x70))

#define CP16(dst, src) \
    asm volatile("cp.async.cg.shared.global [%0], [%1], 16;" :: "r"(dst), "l"(src) : "memory")

__device__ __forceinline__ uint32_t smem_u32(const void* p) {
    uint32_t a;
    asm("{ .reg .u64 t; cvta.to.shared.u64 t, %1; cvt.u32.u64 %0, t; }" : "=r"(a) : "l"(p));
    return a;
}

#define LDSM_X4(r, addr) \
    asm volatile("ldmatrix.sync.aligned.m8n8.x4.shared.b16 {%0,%1,%2,%3}, [%4];" \
        : "=r"((r)[0]), "=r"((r)[1]), "=r"((r)[2]), "=r"((r)[3]) : "r"(addr))

#define MMA16816(c, a, b0, b1) \
    asm volatile("mma.sync.aligned.m16n8k16.row.col.f32.f16.f16.f32 " \
        "{%0,%1,%2,%3}, {%4,%5,%6,%7}, {%8,%9}, {%0,%1,%2,%3};" \
        : "+f"((c)[0]), "+f"((c)[1]), "+f"((c)[2]), "+f"((c)[3]) \
        : "r"((a)[0]), "r"((a)[1]), "r"((a)[2]), "r"((a)[3]), "r"(b0), "r"(b1))

// ---------------- fused prep + x-convert -------------------------------------
// All blocks: convert one 256-float4 slice of x to fp16.
// Blocks 0..255: additionally transpose one 32x32 tile of B_re/B_im/C_re/C_im
//                into W1 (fp16, [2n+comp][t]) and C2 (fp16 half2 (re,-im), [t][n]).
// Block 256: lambda + lambda^CHUNK tables.
__global__ void prep_convert(const float* __restrict__ x,
                             const float* __restrict__ B_re, const float* __restrict__ B_im,
                             const float* __restrict__ C_re, const float* __restrict__ C_im,
                             const float* __restrict__ gamma_log,
                             const float* __restrict__ nu_log,
                             const float* __restrict__ theta_log)
{
    // ---- convert_x slice (all blocks) ----
    {
        size_t i = (size_t)blockIdx.x * blockDim.x + threadIdx.x;   // 4.19M float4
        float4 v = ((const float4*)x)[i];
        __half2 a; a.x = __float2half(v.x); a.y = __float2half(v.y);
        __half2 b; b.x = __float2half(v.z); b.y = __float2half(v.w);
        __half2* H = (__half2*)g_xhi;
        H[2*i] = a; H[2*i+1] = b;
    }

    if (blockIdx.x < 256) {
        // ---- coalesced transposed prep tile ----
        __shared__ float sRe[32][33], sIm[32][33], sCr[32][33], sCi[32][33];
        const int bx = blockIdx.x & 15;    // t-tile
        const int by = blockIdx.x >> 4;    // n-tile
        const int t0 = bx * 32, n0 = by * 32;
        const int tx = threadIdx.x & 31;
        const int ty0 = threadIdx.x >> 5;  // 0..7
#pragma unroll
        for (int i = 0; i < 4; ++i) {
            int ty = ty0 + i * 8;
            sRe[ty][tx] = B_re[(size_t)(t0 + ty) * DIM + n0 + tx];   // [t][n]
            sIm[ty][tx] = B_im[(size_t)(t0 + ty) * DIM + n0 + tx];
            sCr[ty][tx] = C_re[(size_t)(n0 + ty) * DMODEL + t0 + tx]; // [n][t]
            sCi[ty][tx] = C_im[(size_t)(n0 + ty) * DMODEL + t0 + tx];
        }
        __syncthreads();
#pragma unroll
        for (int i = 0; i < 4; ++i) {
            int ty = ty0 + i * 8;
            // W1 rows 2n, 2n+1 (n = n0+ty), cols t0+tx (coalesced in tx)
            int n = n0 + ty;
            float g = expf(gamma_log[n]);
            g_W1[(size_t)(2 * n)     * DMODEL + t0 + tx] = __float2half(sRe[tx][ty] * g);
            g_W1[(size_t)(2 * n + 1) * DMODEL + t0 + tx] = __float2half(sIm[tx][ty] * g);
            // C2 row t = t0+ty, complex col n = n0+tx (coalesced half2 in tx)
            __half2 v;
            v.x = __float2half( sCr[tx][ty]);
            v.y = __float2half(-sCi[tx][ty]);
            ((__half2*)g_C2)[(size_t)(t0 + ty) * (N1 / 2) + n0 + tx] = v;
        }
    } else if (blockIdx.x == 256) {
        // ---- lambda tables (512 t, 2 per thread) ----
#pragma unroll
        for (int i = 0; i < 2; ++i) {
            int t = threadIdx.x + i * 256;
            float r  = expf(-expf(nu_log[t]));
            float th = expf(theta_log[t]);
            float lr = r * cosf(th), li = r * sinf(th);
            g_lam[t] = make_float2(lr, li);
            float ar = 1.f, ai = 0.f;
            for (int k = 0; k < CHUNK; k++) {
                float nr = ar * lr - ai * li;
                float ni = ar * li + ai * lr;
                ar = nr; ai = ni;
            }
            g_lamP[t] = make_float2(ar, ai);
        }
    }
}

// ---------------- fp16 GEMM: BM=128, BN param, 4 warps, 3-stage -------------
// D[m][n] = sum_k A[m][k]*B[n][k]; fp16 K-major both, fp32 accum, SW128.
// SUMS (GEMM1 only): two 64-row chunk-local scan sums per complex column.
#define NSTAGE 3

template<int KDIM, int BN>
__device__ __forceinline__ void fill_tile(uint32_t st, int tid, int row0, int n0, int k0,
    const __half* __restrict__ A, const __half* __restrict__ Bw)
{
    constexpr int ITER = 8 + BN / 16;
#pragma unroll
    for (int i = 0; i < ITER; ++i) {
        int ch = tid + i * 128;
        if (ch < 1024) {   // A: 128 rows x 8 16B-chunks
            int r = ch >> 3, c = ch & 7;
            CP16(st + SWZ((uint32_t)(r * 128 + c * 16)),
                 A + (size_t)(row0 + r) * KDIM + k0 + c * 8);
        } else {           // B: BN rows x 8 16B-chunks
            int bc = ch - 1024;
            int r = bc >> 3, c = bc & 7;
            CP16(st + 16384 + SWZ((uint32_t)(r * 128 + c * 16)),
                 Bw + (size_t)(n0 + r) * KDIM + k0 + c * 8);
        }
    }
    asm volatile("cp.async.commit_group;" ::: "memory");
}

template<int KDIM, int BN, bool HALF_OUT, bool EPI, bool SUMS, int MAXCTA>
__global__ __launch_bounds__(128, MAXCTA) void lru_gemm(
    const __half* __restrict__ A, const __half* __restrict__ Bw,
    void* __restrict__ Cout, int Ntot,
    const float* __restrict__ xres, const float* __restrict__ Dp)
{
    constexpr int STAGE_BYTES = 16384 + BN * 128;
    constexpr int WN = BN / 2;        // warp n-extent
    constexpr int NB = WN / 8;        // 8-col fragments per warp
    constexpr int NG = WN / 16;       // 16-row B ldmatrix groups

    extern __shared__ __align__(1024) char smem[];
    const uint32_t sb = smem_u32(smem);
    const int tid = threadIdx.x;
    const int wid = tid >> 5;
    const int lane = tid & 31;
    const int warp_m = wid & 1;
    const int warp_n = wid >> 1;
    const int row0 = blockIdx.y * 128;
    const int n0   = blockIdx.x * BN;
    constexpr int NK = KDIM / 64;

    float acc[4][NB][4];
#pragma unroll
    for (int mb = 0; mb < 4; mb++)
#pragma unroll
        for (int nb = 0; nb < NB; nb++)
#pragma unroll
            for (int r = 0; r < 4; r++) acc[mb][nb][r] = 0.f;

    const int lrow  = lane & 15;
    const int khalf = lane >> 4;

    fill_tile<KDIM, BN>(sb,               tid, row0, n0, 0,  A, Bw);
    fill_tile<KDIM, BN>(sb + STAGE_BYTES, tid, row0, n0, 64, A, Bw);

    int stage = 0;
    for (int it = 0; it < NK; ++it) {
        const uint32_t st = sb + (uint32_t)stage * STAGE_BYTES;
        if (it + 2 < NK) {
            int ns = stage + 2; if (ns >= NSTAGE) ns -= NSTAGE;
            fill_tile<KDIM, BN>(sb + (uint32_t)ns * STAGE_BYTES, tid,
                                row0, n0, (it + 2) * 64, A, Bw);
            asm volatile("cp.async.wait_group 2;" ::: "memory");
        } else if (it + 1 < NK) {
            asm volatile("cp.async.wait_group 1;" ::: "memory");
        } else {
            asm volatile("cp.async.wait_group 0;" ::: "memory");
        }
        __syncthreads();

#pragma unroll
        for (int ks = 0; ks < 4; ++ks) {
            const uint32_t kb = (uint32_t)(ks * 32 + khalf * 16);
            uint32_t fa[4][4], fb[NG][4];
#pragma unroll
            for (int mb = 0; mb < 4; mb++) {
                uint32_t off = SWZ((uint32_t)((warp_m * 64 + mb * 16 + lrow) * 128) + kb);
                LDSM_X4(fa[mb], st + off);
            }
#pragma unroll
            for (int g = 0; g < NG; g++) {
                uint32_t off = SWZ((uint32_t)((warp_n * WN + g * 16 + lrow) * 128) + kb);
                LDSM_X4(fb[g], st + 16384 + off);
            }
#pragma unroll
            for (int mb = 0; mb < 4; mb++)
#pragma unroll
                for (int nb = 0; nb < NB; nb++) {
                    const int g = nb >> 1, s = nb & 1;
                    MMA16816(acc[mb][nb], fa[mb], fb[g][s], fb[g][s + 2]);
                }
        }
        __syncthreads();
        if (++stage >= NSTAGE) stage = 0;
    }

    // Epilogue: m16n8 frag -> rows lane/4 (+8), cols (lane&3)*2 (+1)
    const int erow_l = warp_m * 64 + (lane >> 2);
    const int ecol_l = warp_n * WN + (lane & 3) * 2;
#pragma unroll
    for (int mb = 0; mb < 4; mb++) {
#pragma unroll
        for (int half = 0; half < 2; half++) {
            const int row = row0 + erow_l + mb * 16 + half * 8;
            if (HALF_OUT) {
                __half* cp = (__half*)Cout + (size_t)row * Ntot;
#pragma unroll
                for (int nb = 0; nb < NB; nb++) {
                    const int col = n0 + ecol_l + nb * 8;
                    __half2 v;
                    v.x = __float2half(acc[mb][nb][half * 2]);
                    v.y = __float2half(acc[mb][nb][half * 2 + 1]);
                    *(__half2*)(cp + col) = v;
                }
            } else {
                float* cp = (float*)Cout + (size_t)row * Ntot;
                const float* xp = EPI ? (xres + (size_t)row * Ntot) : nullptr;
#pragma unroll
                for (int nb = 0; nb < NB; nb++) {
                    const int col = n0 + ecol_l + nb * 8;
                    float2 v = make_float2(acc[mb][nb][half * 2], acc[mb][nb][half * 2 + 1]);
                    if (EPI) {
                        float2 xv = *(const float2*)(xp + col);
                        float2 dv = *(const float2*)(Dp + col);
                        v.x = fmaf(dv.x, xv.x, v.x);
                        v.y = fmaf(dv.y, xv.y, v.y);
                    }
                    *(float2*)(cp + col) = v;
                }
            }
        }
    }

    if (SUMS) {
        // This CTA's 128 rows = two 64-row chunks (bb = by>>5, cc = by&31 ->
        // chunk indices 2cc, 2cc+1); columns are 64 complex n (interleaved).
        const int bb = blockIdx.y >> 5;
        const int cc = blockIdx.y & 31;
        float* tile = (float*)smem;              // 128 rows x 132 floats
        __syncthreads();                         // stages dead; reuse
#pragma unroll
        for (int mb = 0; mb < 4; mb++)
#pragma unroll
            for (int half = 0; half < 2; half++) {
                int r = erow_l + mb * 16 + half * 8;
#pragma unroll
                for (int nb = 0; nb < NB; nb++) {
                    int cl = ecol_l + nb * 8;
                    *(float2*)(tile + r * 132 + cl) =
                        make_float2(acc[mb][nb][half * 2], acc[mb][nb][half * 2 + 1]);
                }
            }
        __syncthreads();

        const int j = tid & 63;                  // complex column within tile
        const int up = tid >> 6;                 // 0: rows 0-63, 1: rows 64-127
        const int nc = (n0 >> 1) + j;
        float2 lam = g_lam[nc];
        float sr = 0.f, si = 0.f;
        const float* colp = tile + (up * 64) * 132 + 2 * j;
#pragma unroll 4
        for (int t = 0; t < 64; t++) {
            float br = colp[0], bi = colp[1];
            float nr = fmaf(lam.x, sr, fmaf(-lam.y, si, br));
            float ni = fmaf(lam.x, si, fmaf( lam.y, sr, bi));
            sr = nr; si = ni;
            colp += 132;
        }
        g_sum[(((cc << 1) | up) * 8 + bb) * 512 + nc] = make_float2(sr, si);
    }
}

// ---------------- scan: 2-state carry Horner + 8-deep pipelined replay ------
// thread (b, c, n2): states n = 2*n2, 2*n2+1. Carry via Horner over g_sum
// (L2-resident), then 64-step replay with a manual 8-deep load pipeline so
// LDGs are issued 8 iterations ahead of use (defeats alias serialization).
__global__ void scan_carry(const float* __restrict__ h0,
                           float* __restrict__ tail, int tail_mode)
{
    int gid = blockIdx.x * blockDim.x + threadIdx.x;   // 131072
    int n2 = gid & 255;
    int n  = n2 * 2;
    int b  = (gid >> 8) & 7;
    int c  = gid >> 11;                                // 0..63
    float2 lam0 = g_lam[n], lam1 = g_lam[n + 1];
    float2 lp0  = g_lamP[n], lp1 = g_lamP[n + 1];
    float c0r = h0[b * DIM + n],     c0i = 0.f;
    float c1r = h0[b * DIM + n + 1], c1i = 0.f;
    for (int j = 0; j < c; ++j) {
        float4 s = *(const float4*)&g_sum[(j * 8 + b) * 512 + n];
        float n0r = fmaf(lp0.x, c0r, fmaf(-lp0.y, c0i, s.x));
        float n0i = fmaf(lp0.x, c0i, fmaf( lp0.y, c0r, s.y));
        float n1r = fmaf(lp1.x, c1r, fmaf(-lp1.y, c1i, s.z));
        float n1i = fmaf(lp1.x, c1i, fmaf( lp1.y, c1r, s.w));
        c0r = n0r; c0i = n0i; c1r = n1r; c1i = n1i;
    }
    size_t base = (size_t)(b * TLEN + c * CHUNK) * N1 + 2 * n;
    const uint2* p = (const uint2*)(g_Buh + base);     // 8B = 2 complex (n, n+1)
    uint2* ph = (uint2*)(g_Hhi + base);

    uint2 buf[8];
#pragma unroll
    for (int i = 0; i < 8; i++) buf[i] = __ldcs(p + (size_t)i * (N1 / 4));

    for (int blk = 0; blk < 8; ++blk) {
        const uint2* pn = p + (size_t)(blk + 1) * 8 * (N1 / 4);
#pragma unroll
        for (int u = 0; u < 8; ++u) {
            uint2 raw = buf[u];
            if (blk < 7) buf[u] = __ldcs(pn + (size_t)u * (N1 / 4));  // load +8 ahead
            float2 b0 = __half22float2(*reinterpret_cast<const __half2*>(&raw.x));
            float2 b1 = __half22float2(*reinterpret_cast<const __half2*>(&raw.y));
            float n0r = fmaf(lam0.x, c0r, fmaf(-lam0.y, c0i, b0.x));
            float n0i = fmaf(lam0.x, c0i, fmaf( lam0.y, c0r, b0.y));
            float n1r = fmaf(lam1.x, c1r, fmaf(-lam1.y, c1i, b1.x));
            float n1i = fmaf(lam1.x, c1i, fmaf( lam1.y, c1r, b1.y));
            c0r = n0r; c0i = n0i; c1r = n1r; c1i = n1i;
            __half2 v0; v0.x = __float2half(n0r); v0.y = __float2half(n0i);
            __half2 v1; v1.x = __float2half(n1r); v1.y = __float2half(n1i);
            uint2 outv;
            outv.x = *reinterpret_cast<uint32_t*>(&v0);
            outv.y = *reinterpret_cast<uint32_t*>(&v1);
            ph[(size_t)(blk * 8 + u) * (N1 / 4)] = outv;
        }
    }
    if (c == NCHUNK - 1) {
        if (tail_mode == 2) {
            *(float4*)&tail[(b * DIM + n) * 2] = make_float4(c0r, c0i, c1r, c1i);
        } else if (tail_mode == 1) {
            *(float2*)&tail[b * DIM + n] = make_float2(c0r, c1r);
        }
    }
}

// ---------------- launch ----------------------------------------------------
extern "C" void kernel_launch(void* const* d_in, const int* in_sizes, int n_in,
                              void* d_out, int out_size)
{
    const float* x         = (const float*)d_in[0];
    const float* h0        = (const float*)d_in[1];
    const float* nu_log    = (const float*)d_in[2];
    const float* theta_log = (const float*)d_in[3];
    const float* B_re      = (const float*)d_in[4];
    const float* B_im      = (const float*)d_in[5];
    const float* C_re      = (const float*)d_in[6];
    const float* C_im      = (const float*)d_in[7];
    const float* D_param   = (const float*)d_in[8];
    const float* gamma_log = (const float*)d_in[9];
    float* out = (float*)d_out;

    __half *pBuh, *pxhi, *pHhi, *pW1, *pC2;
    cudaGetSymbolAddress((void**)&pBuh, g_Buh);
    cudaGetSymbolAddress((void**)&pxhi, g_xhi);
    cudaGetSymbolAddress((void**)&pHhi, g_Hhi);
    cudaGetSymbolAddress((void**)&pW1,  g_W1);
    cudaGetSymbolAddress((void**)&pC2,  g_C2);

    const int SMEM1 = NSTAGE * (16384 + 128 * 128);   // 98304
    const int SMEM2 = NSTAGE * (16384 + 64 * 128);    // 73728
    cudaFuncSetAttribute((const void*)lru_gemm<512, 128, true, false, true, 2>,
                         cudaFuncAttributeMaxDynamicSharedMemorySize, SMEM1);
    cudaFuncSetAttribute((const void*)lru_gemm<1024, 64, false, true, false, 3>,
                         cudaFuncAttributeMaxDynamicSharedMemorySize, SMEM2);

    // 1) fused prep (coalesced transpose) + x convert + lambda tables
    prep_convert<<<(M_ROWS * DMODEL / 4) / 256, 256>>>(
        x, B_re, B_im, C_re, C_im, gamma_log, nu_log, theta_log);

    // 2) GEMM1 + fused chunk sums: Bu[32768 x 1024] = x @ W1 (interleaved)
    lru_gemm<512, 128, true, false, true, 2><<<dim3(N1 / 128, M_ROWS / 128), 128, SMEM1>>>(
        pxhi, pW1, pBuh, N1, nullptr, nullptr);

    // 3) scan with per-thread carry reconstruction (Bu fp16 -> H fp16)
    const long long y_elems = (long long)M_ROWS * DMODEL;
    long long tail_elems = (long long)out_size - y_elems;
    int tail_mode = 0;
    if (tail_elems >= 2LL * BATCH * DIM)           tail_mode = 2;
    else if (tail_elems >= (long long)BATCH * DIM) tail_mode = 1;
    scan_carry<<<(NCHUNK * BATCH * DIM / 2) / 256, 256>>>(h0, out + y_elems, tail_mode);

    // 4) GEMM2: y[32768 x 512] = H @ C2 + D*x (fp32 out, 128x64 tiles)
    lru_gemm<1024, 64, false, true, false, 3><<<dim3(DMODEL / 64, M_ROWS / 128), 128, SMEM2>>>(
        pHhi, pC2, out, DMODEL, x, D_param);
}

// round 16
// speedup vs baseline: 1.1943x; 1.0174x over previous
#include <cuda_runtime.h>
#include <cuda_fp16.h>
#include <math.h>
#include <stdint.h>

// Problem constants
#define BATCH   8
#define TLEN    4096
#define DMODEL  512
#define DIM     512
#define M_ROWS  (BATCH*TLEN)   /* 32768 */
#define N1      1024           /* interleaved: col 2n = re_n, 2n+1 = im_n */
#define CHUNK   64
#define NCHUNK  (TLEN/CHUNK)   /* 64 */

// ---------------- scratch (device globals; no allocation allowed) -----------
__device__ __half g_Buh[(size_t)M_ROWS * N1];      // 64 MB fp16 (GEMM1 out, scan in)
__device__ __half g_xhi[(size_t)M_ROWS * DMODEL];  // 32 MB
__device__ __half g_Hhi[(size_t)M_ROWS * N1];      // 64 MB
__device__ __half g_W1 [N1 * DMODEL];              // [col=2n+comp][k=512] fp16
__device__ __half g_C2 [DMODEL * N1];              // [d=512][kk=2n+comp] fp16
__device__ float2 g_lam [DIM];
__device__ float2 g_lamP[DIM];                     // Lambda^CHUNK (=^64)
__device__ float2 g_sum[NCHUNK * BATCH * DIM];     // 2 MB (L2-resident)

// ---------------- PTX helpers -----------------------------------------------
#define SWZ(o) ((o) ^ (((o) >> 3) & 0x70))

#define CP16(dst, src) \
    asm volatile("cp.async.cg.shared.global [%0], [%1], 16;" :: "r"(dst), "l"(src) : "memory")

__device__ __forceinline__ uint32_t smem_u32(const void* p) {
    uint32_t a;
    asm("{ .reg .u64 t; cvta.to.shared.u64 t, %1; cvt.u32.u64 %0, t; }" : "=r"(a) : "l"(p));
    return a;
}

#define LDSM_X4(r, addr) \
    asm volatile("ldmatrix.sync.aligned.m8n8.x4.shared.b16 {%0,%1,%2,%3}, [%4];" \
        : "=r"((r)[0]), "=r"((r)[1]), "=r"((r)[2]), "=r"((r)[3]) : "r"(addr))

#define MMA16816(c, a, b0, b1) \
    asm volatile("mma.sync.aligned.m16n8k16.row.col.f32.f16.f16.f32 " \
        "{%0,%1,%2,%3}, {%4,%5,%6,%7}, {%8,%9}, {%0,%1,%2,%3};" \
        : "+f"((c)[0]), "+f"((c)[1]), "+f"((c)[2]), "+f"((c)[3]) \
        : "r"((a)[0]), "r"((a)[1]), "r"((a)[2]), "r"((a)[3]), "r"(b0), "r"(b1))

// ---------------- fused prep + x-convert -------------------------------------
__global__ void prep_convert(const float* __restrict__ x,
                             const float* __restrict__ B_re, const float* __restrict__ B_im,
                             const float* __restrict__ C_re, const float* __restrict__ C_im,
                             const float* __restrict__ gamma_log,
                             const float* __restrict__ nu_log,
                             const float* __restrict__ theta_log)
{
    // ---- convert_x slice (all blocks) ----
    {
        size_t i = (size_t)blockIdx.x * blockDim.x + threadIdx.x;   // 4.19M float4
        float4 v = ((const float4*)x)[i];
        __half2 a; a.x = __float2half(v.x); a.y = __float2half(v.y);
        __half2 b; b.x = __float2half(v.z); b.y = __float2half(v.w);
        __half2* H = (__half2*)g_xhi;
        H[2*i] = a; H[2*i+1] = b;
    }

    if (blockIdx.x < 256) {
        // ---- coalesced transposed prep tile ----
        __shared__ float sRe[32][33], sIm[32][33], sCr[32][33], sCi[32][33];
        const int bx = blockIdx.x & 15;    // t-tile
        const int by = blockIdx.x >> 4;    // n-tile
        const int t0 = bx * 32, n0 = by * 32;
        const int tx = threadIdx.x & 31;
        const int ty0 = threadIdx.x >> 5;  // 0..7
#pragma unroll
        for (int i = 0; i < 4; ++i) {
            int ty = ty0 + i * 8;
            sRe[ty][tx] = B_re[(size_t)(t0 + ty) * DIM + n0 + tx];   // [t][n]
            sIm[ty][tx] = B_im[(size_t)(t0 + ty) * DIM + n0 + tx];
            sCr[ty][tx] = C_re[(size_t)(n0 + ty) * DMODEL + t0 + tx]; // [n][t]
            sCi[ty][tx] = C_im[(size_t)(n0 + ty) * DMODEL + t0 + tx];
        }
        __syncthreads();
#pragma unroll
        for (int i = 0; i < 4; ++i) {
            int ty = ty0 + i * 8;
            int n = n0 + ty;
            float g = expf(gamma_log[n]);
            g_W1[(size_t)(2 * n)     * DMODEL + t0 + tx] = __float2half(sRe[tx][ty] * g);
            g_W1[(size_t)(2 * n + 1) * DMODEL + t0 + tx] = __float2half(sIm[tx][ty] * g);
            __half2 v;
            v.x = __float2half( sCr[tx][ty]);
            v.y = __float2half(-sCi[tx][ty]);
            ((__half2*)g_C2)[(size_t)(t0 + ty) * (N1 / 2) + n0 + tx] = v;
        }
    } else if (blockIdx.x == 256) {
        // ---- lambda tables ----
#pragma unroll
        for (int i = 0; i < 2; ++i) {
            int t = threadIdx.x + i * 256;
            float r  = expf(-expf(nu_log[t]));
            float th = expf(theta_log[t]);
            float lr = r * cosf(th), li = r * sinf(th);
            g_lam[t] = make_float2(lr, li);
            float ar = 1.f, ai = 0.f;
            for (int k = 0; k < CHUNK; k++) {
                float nr = ar * lr - ai * li;
                float ni = ar * li + ai * lr;
                ar = nr; ai = ni;
            }
            g_lamP[t] = make_float2(ar, ai);
        }
    }
}

// ---------------- fp16 GEMM: BM=128, BN=128, 4 warps (64x64), 3-stage -------
// D[m][n] = sum_k A[m][k]*B[n][k]; fp16 K-major both, fp32 accum, SW128.
// Register fragment double-buffering: LDSM for ks+1 issued before MMAs on ks,
// breaking the LDSM/MMA phase-lock (tensor and smem crossbar overlap).
// SUMS (GEMM1 only): two 64-row chunk-local scan sums per complex column.
#define NSTAGE 3

template<int KDIM, int BN>
__device__ __forceinline__ void fill_tile(uint32_t st, int tid, int row0, int n0, int k0,
    const __half* __restrict__ A, const __half* __restrict__ Bw)
{
    constexpr int ITER = 8 + BN / 16;
#pragma unroll
    for (int i = 0; i < ITER; ++i) {
        int ch = tid + i * 128;
        if (ch < 1024) {   // A: 128 rows x 8 16B-chunks
            int r = ch >> 3, c = ch & 7;
            CP16(st + SWZ((uint32_t)(r * 128 + c * 16)),
                 A + (size_t)(row0 + r) * KDIM + k0 + c * 8);
        } else {           // B: BN rows x 8 16B-chunks
            int bc = ch - 1024;
            int r = bc >> 3, c = bc & 7;
            CP16(st + 16384 + SWZ((uint32_t)(r * 128 + c * 16)),
                 Bw + (size_t)(n0 + r) * KDIM + k0 + c * 8);
        }
    }
    asm volatile("cp.async.commit_group;" ::: "memory");
}

template<int KDIM, int BN, bool HALF_OUT, bool EPI, bool SUMS, int MAXCTA>
__global__ __launch_bounds__(128, MAXCTA) void lru_gemm(
    const __half* __restrict__ A, const __half* __restrict__ Bw,
    void* __restrict__ Cout, int Ntot,
    const float* __restrict__ xres, const float* __restrict__ Dp)
{
    constexpr int STAGE_BYTES = 16384 + BN * 128;
    constexpr int WN = BN / 2;        // warp n-extent
    constexpr int NB = WN / 8;        // 8-col fragments per warp
    constexpr int NG = WN / 16;       // 16-row B ldmatrix groups

    extern __shared__ __align__(1024) char smem[];
    const uint32_t sb = smem_u32(smem);
    const int tid = threadIdx.x;
    const int wid = tid >> 5;
    const int lane = tid & 31;
    const int warp_m = wid & 1;
    const int warp_n = wid >> 1;
    const int row0 = blockIdx.y * 128;
    const int n0   = blockIdx.x * BN;
    constexpr int NK = KDIM / 64;

    float acc[4][NB][4];
#pragma unroll
    for (int mb = 0; mb < 4; mb++)
#pragma unroll
        for (int nb = 0; nb < NB; nb++)
#pragma unroll
            for (int r = 0; r < 4; r++) acc[mb][nb][r] = 0.f;

    const int lrow  = lane & 15;
    const int khalf = lane >> 4;

    // register fragment double buffers
    uint32_t fa[2][4][4], fb[2][NG][4];

#define LOAD_FRAGS(B_, st_, ks_) do {                                               \
        const uint32_t kb_ = (uint32_t)((ks_) * 32 + khalf * 16);                   \
        _Pragma("unroll")                                                           \
        for (int mb_ = 0; mb_ < 4; mb_++) {                                         \
            uint32_t off_ = SWZ((uint32_t)((warp_m*64 + mb_*16 + lrow)*128) + kb_); \
            LDSM_X4(fa[B_][mb_], (st_) + off_);                                     \
        }                                                                           \
        _Pragma("unroll")                                                           \
        for (int g_ = 0; g_ < NG; g_++) {                                           \
            uint32_t off_ = SWZ((uint32_t)((warp_n*WN + g_*16 + lrow)*128) + kb_);  \
            LDSM_X4(fb[B_][g_], (st_) + 16384 + off_);                              \
        }                                                                           \
    } while (0)

    fill_tile<KDIM, BN>(sb,               tid, row0, n0, 0,  A, Bw);
    fill_tile<KDIM, BN>(sb + STAGE_BYTES, tid, row0, n0, 64, A, Bw);

    int stage = 0;
    for (int it = 0; it < NK; ++it) {
        const uint32_t st = sb + (uint32_t)stage * STAGE_BYTES;
        if (it + 2 < NK) {
            int ns = stage + 2; if (ns >= NSTAGE) ns -= NSTAGE;
            fill_tile<KDIM, BN>(sb + (uint32_t)ns * STAGE_BYTES, tid,
                                row0, n0, (it + 2) * 64, A, Bw);
            asm volatile("cp.async.wait_group 2;" ::: "memory");
        } else if (it + 1 < NK) {
            asm volatile("cp.async.wait_group 1;" ::: "memory");
        } else {
            asm volatile("cp.async.wait_group 0;" ::: "memory");
        }
        __syncthreads();

        LOAD_FRAGS(0, st, 0);
#pragma unroll
        for (int ks = 0; ks < 4; ++ks) {
            const int cur = ks & 1;
            if (ks < 3) LOAD_FRAGS(cur ^ 1, st, ks + 1);   // overlap next LDSM with MMAs
#pragma unroll
            for (int mb = 0; mb < 4; mb++)
#pragma unroll
                for (int nb = 0; nb < NB; nb++) {
                    const int g = nb >> 1, s = nb & 1;
                    MMA16816(acc[mb][nb], fa[cur][mb], fb[cur][g][s], fb[cur][g][s + 2]);
                }
        }
        __syncthreads();
        if (++stage >= NSTAGE) stage = 0;
    }
#undef LOAD_FRAGS

    // Epilogue: m16n8 frag -> rows lane/4 (+8), cols (lane&3)*2 (+1)
    const int erow_l = warp_m * 64 + (lane >> 2);
    const int ecol_l = warp_n * WN + (lane & 3) * 2;
#pragma unroll
    for (int mb = 0; mb < 4; mb++) {
#pragma unroll
        for (int half = 0; half < 2; half++) {
            const int row = row0 + erow_l + mb * 16 + half * 8;
            if (HALF_OUT) {
                __half* cp = (__half*)Cout + (size_t)row * Ntot;
#pragma unroll
                for (int nb = 0; nb < NB; nb++) {
                    const int col = n0 + ecol_l + nb * 8;
                    __half2 v;
                    v.x = __float2half(acc[mb][nb][half * 2]);
                    v.y = __float2half(acc[mb][nb][half * 2 + 1]);
                    *(__half2*)(cp + col) = v;
                }
            } else {
                float* cp = (float*)Cout + (size_t)row * Ntot;
                const float* xp = EPI ? (xres + (size_t)row * Ntot) : nullptr;
#pragma unroll
                for (int nb = 0; nb < NB; nb++) {
                    const int col = n0 + ecol_l + nb * 8;
                    float2 v = make_float2(acc[mb][nb][half * 2], acc[mb][nb][half * 2 + 1]);
                    if (EPI) {
                        float2 xv = *(const float2*)(xp + col);
                        float2 dv = *(const float2*)(Dp + col);
                        v.x = fmaf(dv.x, xv.x, v.x);
                        v.y = fmaf(dv.y, xv.y, v.y);
                    }
                    *(float2*)(cp + col) = v;
                }
            }
        }
    }

    if (SUMS) {
        // This CTA's 128 rows = two 64-row chunks (bb = by>>5, cc = by&31 ->
        // chunk indices 2cc, 2cc+1); columns are 64 complex n (interleaved).
        const int bb = blockIdx.y >> 5;
        const int cc = blockIdx.y & 31;
        float* tile = (float*)smem;              // 128 rows x 132 floats
        __syncthreads();                         // stages dead; reuse
#pragma unroll
        for (int mb = 0; mb < 4; mb++)
#pragma unroll
            for (int half = 0; half < 2; half++) {
                int r = erow_l + mb * 16 + half * 8;
#pragma unroll
                for (int nb = 0; nb < NB; nb++) {
                    int cl = ecol_l + nb * 8;
                    *(float2*)(tile + r * 132 + cl) =
                        make_float2(acc[mb][nb][half * 2], acc[mb][nb][half * 2 + 1]);
                }
            }
        __syncthreads();

        const int j = tid & 63;                  // complex column within tile
        const int up = tid >> 6;                 // 0: rows 0-63, 1: rows 64-127
        const int nc = (n0 >> 1) + j;
        float2 lam = g_lam[nc];
        float sr = 0.f, si = 0.f;
        const float* colp = tile + (up * 64) * 132 + 2 * j;
#pragma unroll 4
        for (int t = 0; t < 64; t++) {
            float br = colp[0], bi = colp[1];
            float nr = fmaf(lam.x, sr, fmaf(-lam.y, si, br));
            float ni = fmaf(lam.x, si, fmaf( lam.y, sr, bi));
            sr = nr; si = ni;
            colp += 132;
        }
        g_sum[(((cc << 1) | up) * 8 + bb) * 512 + nc] = make_float2(sr, si);
    }
}

// ---------------- scan: 2-state carry Horner + 8-deep pipelined replay ------
__global__ void scan_carry(const float* __restrict__ h0,
                           float* __restrict__ tail, int tail_mode)
{
    int gid = blockIdx.x * blockDim.x + threadIdx.x;   // 131072
    int n2 = gid & 255;
    int n  = n2 * 2;
    int b  = (gid >> 8) & 7;
    int c  = gid >> 11;                                // 0..63
    float2 lam0 = g_lam[n], lam1 = g_lam[n + 1];
    float2 lp0  = g_lamP[n], lp1 = g_lamP[n + 1];
    float c0r = h0[b * DIM + n],     c0i = 0.f;
    float c1r = h0[b * DIM + n + 1], c1i = 0.f;
    for (int j = 0; j < c; ++j) {
        float4 s = *(const float4*)&g_sum[(j * 8 + b) * 512 + n];
        float n0r = fmaf(lp0.x, c0r, fmaf(-lp0.y, c0i, s.x));
        float n0i = fmaf(lp0.x, c0i, fmaf( lp0.y, c0r, s.y));
        float n1r = fmaf(lp1.x, c1r, fmaf(-lp1.y, c1i, s.z));
        float n1i = fmaf(lp1.x, c1i, fmaf( lp1.y, c1r, s.w));
        c0r = n0r; c0i = n0i; c1r = n1r; c1i = n1i;
    }
    size_t base = (size_t)(b * TLEN + c * CHUNK) * N1 + 2 * n;
    const uint2* p = (const uint2*)(g_Buh + base);     // 8B = 2 complex (n, n+1)
    uint2* ph = (uint2*)(g_Hhi + base);

    uint2 buf[8];
#pragma unroll
    for (int i = 0; i < 8; i++) buf[i] = __ldcs(p + (size_t)i * (N1 / 4));

    for (int blk = 0; blk < 8; ++blk) {
        const uint2* pn = p + (size_t)(blk + 1) * 8 * (N1 / 4);
#pragma unroll
        for (int u = 0; u < 8; ++u) {
            uint2 raw = buf[u];
            if (blk < 7) buf[u] = __ldcs(pn + (size_t)u * (N1 / 4));  // load +8 ahead
            float2 b0 = __half22float2(*reinterpret_cast<const __half2*>(&raw.x));
            float2 b1 = __half22float2(*reinterpret_cast<const __half2*>(&raw.y));
            float n0r = fmaf(lam0.x, c0r, fmaf(-lam0.y, c0i, b0.x));
            float n0i = fmaf(lam0.x, c0i, fmaf( lam0.y, c0r, b0.y));
            float n1r = fmaf(lam1.x, c1r, fmaf(-lam1.y, c1i, b1.x));
            float n1i = fmaf(lam1.x, c1i, fmaf( lam1.y, c1r, b1.y));
            c0r = n0r; c0i = n0i; c1r = n1r; c1i = n1i;
            __half2 v0; v0.x = __float2half(n0r); v0.y = __float2half(n0i);
            __half2 v1; v1.x = __float2half(n1r); v1.y = __float2half(n1i);
            uint2 outv;
            outv.x = *reinterpret_cast<uint32_t*>(&v0);
            outv.y = *reinterpret_cast<uint32_t*>(&v1);
            ph[(size_t)(blk * 8 + u) * (N1 / 4)] = outv;
        }
    }
    if (c == NCHUNK - 1) {
        if (tail_mode == 2) {
            *(float4*)&tail[(b * DIM + n) * 2] = make_float4(c0r, c0i, c1r, c1i);
        } else if (tail_mode == 1) {
            *(float2*)&tail[b * DIM + n] = make_float2(c0r, c1r);
        }
    }
}

// ---------------- launch ----------------------------------------------------
extern "C" void kernel_launch(void* const* d_in, const int* in_sizes, int n_in,
                              void* d_out, int out_size)
{
    const float* x         = (const float*)d_in[0];
    const float* h0        = (const float*)d_in[1];
    const float* nu_log    = (const float*)d_in[2];
    const float* theta_log = (const float*)d_in[3];
    const float* B_re      = (const float*)d_in[4];
    const float* B_im      = (const float*)d_in[5];
    const float* C_re      = (const float*)d_in[6];
    const float* C_im      = (const float*)d_in[7];
    const float* D_param   = (const float*)d_in[8];
    const float* gamma_log = (const float*)d_in[9];
    float* out = (float*)d_out;

    __half *pBuh, *pxhi, *pHhi, *pW1, *pC2;
    cudaGetSymbolAddress((void**)&pBuh, g_Buh);
    cudaGetSymbolAddress((void**)&pxhi, g_xhi);
    cudaGetSymbolAddress((void**)&pHhi, g_Hhi);
    cudaGetSymbolAddress((void**)&pW1,  g_W1);
    cudaGetSymbolAddress((void**)&pC2,  g_C2);

    const int SMEM1 = NSTAGE * (16384 + 128 * 128);   // 98304
    cudaFuncSetAttribute((const void*)lru_gemm<512, 128, true, false, true, 2>,
                         cudaFuncAttributeMaxDynamicSharedMemorySize, SMEM1);
    cudaFuncSetAttribute((const void*)lru_gemm<1024, 128, false, true, false, 2>,
                         cudaFuncAttributeMaxDynamicSharedMemorySize, SMEM1);

    // 1) fused prep (coalesced transpose) + x convert + lambda tables
    prep_convert<<<(M_ROWS * DMODEL / 4) / 256, 256>>>(
        x, B_re, B_im, C_re, C_im, gamma_log, nu_log, theta_log);

    // 2) GEMM1 + fused chunk sums: Bu[32768 x 1024] = x @ W1 (interleaved)
    lru_gemm<512, 128, true, false, true, 2><<<dim3(N1 / 128, M_ROWS / 128), 128, SMEM1>>>(
        pxhi, pW1, pBuh, N1, nullptr, nullptr);

    // 3) scan with per-thread carry reconstruction (Bu fp16 -> H fp16)
    const long long y_elems = (long long)M_ROWS * DMODEL;
    long long tail_elems = (long long)out_size - y_elems;
    int tail_mode = 0;
    if (tail_elems >= 2LL * BATCH * DIM)           tail_mode = 2;
    else if (tail_elems >= (long long)BATCH * DIM) tail_mode = 1;
    scan_carry<<<(NCHUNK * BATCH * DIM / 2) / 256, 256>>>(h0, out + y_elems, tail_mode);

    // 4) GEMM2: y[32768 x 512] = H @ C2 + D*x (fp32 out, 128x128 tiles)
    lru_gemm<1024, 128, false, true, false, 2><<<dim3(DMODEL / 128, M_ROWS / 128), 128, SMEM1>>>(
        pHhi, pC2, out, DMODEL, x, D_param);
}